// round 15
// baseline (speedup 1.0000x reference)
#include <cuda_runtime.h>
#include <cuda_fp16.h>
#include <cuda_fp8.h>

#define NN 4096
#define DD 128
#define ITERS 100
#define GRID_SINK 128
#define EPSV 1e-8f
#define MUV (1.0f / 4096.0f)
#define REGC 0.05f
#define USF 64.0f             // u staging scale (half-safe)
#define VS2 1048576.0f        // v storage scale (2^20)

// ---------------- static device scratch (allocation-free rule) ----------------
__device__ __align__(256) unsigned char g_K8[3ULL * NN * NN];  // 48 MB fp8 e4m3
__device__ __align__(256) float g_u[3][NN];                    // true u
__device__ __align__(256) __half g_vsh[3][NN];                 // v'' (v * VS2) as half
__device__ __align__(256) float g_tau[3][GRID_SINK][NN];       // outer-product partials
__device__ __align__(256) float g_sq[3][NN];
__device__ double g_part[3 * GRID_SINK];
__device__ unsigned g_cnt = 0;          // monotonic barrier counter (reset in final_kernel)

// ---------------- fp8 e4m3 helpers ---------------------------------------------
__device__ __forceinline__ unsigned enc4(float a, float b, float c, float d) {
    unsigned short lo = __nv_cvt_float2_to_fp8x2(make_float2(a, b), __NV_SATFINITE, __NV_E4M3);
    unsigned short hi = __nv_cvt_float2_to_fp8x2(make_float2(c, d), __NV_SATFINITE, __NV_E4M3);
    return (unsigned)lo | ((unsigned)hi << 16);
}

__device__ __forceinline__ __half2 dec2h(unsigned short s) {
    __half2_raw r = __nv_cvt_fp8x2_to_halfraw2((__nv_fp8x2_storage_t)s, __NV_E4M3);
    return *reinterpret_cast<__half2*>(&r);
}

// decode 8 fp8 (uint2) -> 4 half2
__device__ __forceinline__ void dec8(uint2 k, __half2* h) {
    h[0] = dec2h((unsigned short)(k.x & 0xFFFFu));
    h[1] = dec2h((unsigned short)(k.x >> 16));
    h[2] = dec2h((unsigned short)(k.y & 0xFFFFu));
    h[3] = dec2h((unsigned short)(k.y >> 16));
}

__device__ __forceinline__ void dec4f(unsigned x, float* f) {
    float2 a = __half22float2(dec2h((unsigned short)(x & 0xFFFFu)));
    float2 b = __half22float2(dec2h((unsigned short)(x >> 16)));
    f[0] = a.x; f[1] = a.y; f[2] = b.x; f[3] = b.y;
}

__device__ __forceinline__ __half2 shflx_h2(__half2 v, int o) {
    unsigned u = *reinterpret_cast<unsigned*>(&v);
    unsigned r = __shfl_xor_sync(0xffffffffu, u, o);
    return *reinterpret_cast<__half2*>(&r);
}

// ---------------- grid-wide barrier (monotonic counter) ------------------------
__device__ __forceinline__ void grid_barrier_t(unsigned target) {
    __syncthreads();
    if (threadIdx.x == 0) {
        __threadfence();                       // release my stores
        atomicAdd(&g_cnt, 1u);
        while (*(volatile unsigned*)&g_cnt < target) { }
        __threadfence();                       // acquire (CCTL.IVALL: L1 flush)
    }
    __syncthreads();
}

// ---------------- row squared norms --------------------------------------------
__global__ void rowsq_kernel(const float* __restrict__ z0, const float* __restrict__ z1,
                             const float* __restrict__ z2) {
    int gw = (blockIdx.x * blockDim.x + threadIdx.x) >> 5;
    int lane = threadIdx.x & 31;
    int which = gw >> 12, row = gw & 4095;
    const float* src = which == 0 ? z0 : (which == 1 ? z1 : z2);
    float4 v = *(const float4*)(src + (size_t)row * DD + lane * 4);
    float s = v.x * v.x + v.y * v.y + v.z * v.z + v.w * v.w;
#pragma unroll
    for (int o = 16; o; o >>= 1) s += __shfl_xor_sync(0xffffffffu, s, o);
    if (lane == 0) g_sq[which][row] = s;
}

// ---------------- build K (fp8 e4m3) for all 3 pairs — HFMA2 GEMM --------------
__global__ void __launch_bounds__(256) build_kernel(const float* __restrict__ z0,
                                                    const float* __restrict__ z1,
                                                    const float* __restrict__ z2) {
    __shared__ __half2 sx[64][66];
    __shared__ __half2 sy[64][66];
    const int pa[3] = {0, 0, 1};
    const int pb[3] = {1, 2, 2};
    const float* zz[3] = {z0, z1, z2};
    const int p = blockIdx.z;
    const float* x = zz[pa[p]];
    const float* y = zz[pb[p]];

    const int tid = threadIdx.x;
    const int tx = tid & 15, ty = tid >> 4;
    const int row0 = blockIdx.y << 6, col0 = blockIdx.x << 6;

#pragma unroll
    for (int q = 0; q < 8; q++) {
        int idx = tid + (q << 8);
        int r = idx >> 5, k4 = idx & 31;
        float4 a = *(const float4*)(x + (size_t)(row0 + r) * DD + k4 * 4);
        sx[r][k4 * 2]     = __floats2half2_rn(a.x, a.y);
        sx[r][k4 * 2 + 1] = __floats2half2_rn(a.z, a.w);
        float4 b = *(const float4*)(y + (size_t)(col0 + r) * DD + k4 * 4);
        sy[r][k4 * 2]     = __floats2half2_rn(b.x, b.y);
        sy[r][k4 * 2 + 1] = __floats2half2_rn(b.z, b.w);
    }
    __syncthreads();

    __half2 z = __half2half2(__ushort_as_half(0));
    __half2 acc[4][4] = {{z, z, z, z}, {z, z, z, z}, {z, z, z, z}, {z, z, z, z}};

#pragma unroll 8
    for (int k = 0; k < 64; k++) {
        __half2 xa[4], yb[4];
#pragma unroll
        for (int a = 0; a < 4; a++) xa[a] = sx[ty * 4 + a][k];
#pragma unroll
        for (int b = 0; b < 4; b++) yb[b] = sy[tx * 4 + b][k];
#pragma unroll
        for (int a = 0; a < 4; a++)
#pragma unroll
            for (int b = 0; b < 4; b++)
                acc[a][b] = __hfma2(xa[a], yb[b], acc[a][b]);
    }

    float xs[4], ys[4];
#pragma unroll
    for (int a = 0; a < 4; a++) xs[a] = g_sq[pa[p]][row0 + ty * 4 + a];
#pragma unroll
    for (int b = 0; b < 4; b++) ys[b] = g_sq[pb[p]][col0 + tx * 4 + b];

    const size_t base = (size_t)p * NN * NN;
#pragma unroll
    for (int a = 0; a < 4; a++) {
        size_t off = base + (size_t)(row0 + ty * 4 + a) * NN + col0 + tx * 4;
        float kk[4];
#pragma unroll
        for (int b = 0; b < 4; b++) {
            float2 d = __half22float2(acc[a][b]);
            float dot = d.x + d.y;
            float c = fmaxf(xs[a] + ys[b] - 2.0f * dot, 0.0f);
            kk[b] = fmaxf(__expf(-20.0f * c), 0.002f);   // clamp above fp8 underflow
        }
        *(unsigned*)(g_K8 + off) = enc4(kk[0], kk[1], kk[2], kk[3]);
    }
}

// ---------------- persistent fused 3-pair Sinkhorn (register K tile) -----------
// CTA c owns rows [c*32, c*32+32). Warp w owns cols [w*256, (w+1)*256);
// lane holds 8 cols (uint2/row). Per pair per iteration K is loaded ONCE into
// registers and used for BOTH the row-dot (C: u) and the column outer-product
// (A: tau). v'' read directly from global half (no smem broadcast).
__global__ void __launch_bounds__(512, 1) sinkhorn_kernel() {
    __shared__ float2 swred[16][16];    // cross-warp dot partials (rows pairwise)
    __shared__ __half2 su2_h[16];       // u*USF packed pairwise (rows 2i, 2i+1)
    __shared__ float sred[12][32];
    const int c = blockIdx.x;
    const int tid = threadIdx.x;
    const int lane = tid & 31, w = tid >> 5;    // 16 warps
    unsigned nb = 0;
    const __half2 h2z = __half2half2(__ushort_as_half(0));

    // ---------- B-step: reduce partials -> v'' (half) -------------------------
    auto phaseB = [&]() {
        if (w < 12) {
            int pb = w >> 2, q = w & 3;
            const float* tp = &g_tau[pb][q * 32][c * 32 + lane];
            float s = 0.0f;
#pragma unroll
            for (int cc = 0; cc < 32; cc++) s += __ldcg(tp + (size_t)cc * NN);
            sred[w][lane] = s;
        }
        __syncthreads();
        if (tid < 96) {
            int pb = tid >> 5, j = tid & 31;
            float tauS = sred[pb * 4][j] + sred[pb * 4 + 1][j] +
                         sred[pb * 4 + 2][j] + sred[pb * 4 + 3][j];
            float tau = tauS * (1.0f / USF);            // true Kt.u
            g_vsh[pb][c * 32 + j] = __float2half_rn((VS2 * MUV) / (tau + EPSV));
        }
        __syncthreads();
    };

    // ---------- fused C(+)A over the register-held 32x256 subtile -------------
    auto fused = [&](int p, bool doC, bool doA) {
        const unsigned char* Kb = g_K8 + (size_t)p * NN * NN +
                                  (size_t)(c * 32) * NN + w * 256 + lane * 8;
        uint2 kraw[32];
#pragma unroll
        for (int r = 0; r < 32; r++)
            kraw[r] = __ldcg((const uint2*)(Kb + (size_t)r * NN));

        if (doC) {
            uint4 vload = __ldcg((const uint4*)(&g_vsh[p][w * 256 + lane * 8]));
            __half2 vh[4];
            vh[0] = *reinterpret_cast<__half2*>(&vload.x);
            vh[1] = *reinterpret_cast<__half2*>(&vload.y);
            vh[2] = *reinterpret_cast<__half2*>(&vload.z);
            vh[3] = *reinterpret_cast<__half2*>(&vload.w);

            __half2 pd[16];
#pragma unroll
            for (int i = 0; i < 16; i++) {
                __half2 h0[4], h1[4];
                dec8(kraw[2 * i], h0);
                dec8(kraw[2 * i + 1], h1);
                __half2 d0 = __hmul2(h0[0], vh[0]);
                d0 = __hfma2(h0[1], vh[1], d0);
                d0 = __hfma2(h0[2], vh[2], d0);
                d0 = __hfma2(h0[3], vh[3], d0);
                __half2 d1 = __hmul2(h1[0], vh[0]);
                d1 = __hfma2(h1[1], vh[1], d1);
                d1 = __hfma2(h1[2], vh[2], d1);
                d1 = __hfma2(h1[3], vh[3], d1);
                // pd[i] = (dot(row 2i), dot(row 2i+1))
                pd[i] = __hadd2(__lows2half2(d0, d1), __highs2half2(d0, d1));
            }
            // butterfly all-reduce across 32 lanes (sum over warp's 256 cols)
#pragma unroll
            for (int o = 1; o <= 16; o <<= 1) {
#pragma unroll
                for (int i = 0; i < 16; i++)
                    pd[i] = __hadd2(pd[i], shflx_h2(pd[i], o));
            }
            if (lane == 0) {
#pragma unroll
                for (int i = 0; i < 16; i++)
                    swred[w][i] = __half22float2(pd[i]);
            }
            __syncthreads();
            if (w == 0 && lane < 16) {
                float2 s = swred[0][lane];
#pragma unroll
                for (int k = 1; k < 16; k++) {
                    float2 t2 = swred[k][lane];
                    s.x += t2.x;
                    s.y += t2.y;
                }
                float u0 = MUV / (s.x * (1.0f / VS2) + EPSV);
                float u1 = MUV / (s.y * (1.0f / VS2) + EPSV);
                g_u[p][c * 32 + 2 * lane]     = u0;
                g_u[p][c * 32 + 2 * lane + 1] = u1;
                su2_h[lane] = __floats2half2_rn(u0 * USF, u1 * USF);
            }
            __syncthreads();
        }

        if (doA) {
            __half2 su2[16];
#pragma unroll
            for (int i = 0; i < 16; i++) su2[i] = su2_h[i];
            __half2 tac[4] = {h2z, h2z, h2z, h2z};
#pragma unroll
            for (int r = 0; r < 32; r++) {
                __half2 kh[4];
                dec8(kraw[r], kh);
                __half uh = (r & 1) ? __high2half(su2[r >> 1]) : __low2half(su2[r >> 1]);
                __half2 ub = __half2half2(uh);
#pragma unroll
                for (int j = 0; j < 4; j++) tac[j] = __hfma2(kh[j], ub, tac[j]);
            }
            float2 t0 = __half22float2(tac[0]), t1 = __half22float2(tac[1]);
            float2 t2 = __half22float2(tac[2]), t3 = __half22float2(tac[3]);
            float* tp = &g_tau[p][c][w * 256 + lane * 8];
            *(float4*)tp = make_float4(t0.x, t0.y, t1.x, t1.y);
            *(float4*)(tp + 4) = make_float4(t2.x, t2.y, t3.x, t3.y);
        }
    };

    // ---------- initial A0 with u = 1 -----------------------------------------
    if (tid < 16) su2_h[tid] = __floats2half2_rn(USF, USF);
    __syncthreads();
#pragma unroll 1
    for (int p = 0; p < 3; p++) fused(p, false, true);
    grid_barrier_t(++nb * GRID_SINK);
    phaseB();
    grid_barrier_t(++nb * GRID_SINK);

    for (int t = 1; t <= ITERS; t++) {
#pragma unroll 1
        for (int p = 0; p < 3; p++) fused(p, true, t < ITERS);
        if (t < ITERS) {
            grid_barrier_t(++nb * GRID_SINK);
            phaseB();
            grid_barrier_t(++nb * GRID_SINK);
        }
    }
}

// ---------------- loss = sum_ij u_i K_ij C_ij v_j,  C = -reg*ln(K) -------------
__global__ void __launch_bounds__(256) loss_kernel() {
    __shared__ float svec[NN];
    __shared__ double sred[8];
    const int c = blockIdx.x;
    const int p = blockIdx.y;
    const int tid = threadIdx.x;
    const int lane = tid & 31, w = tid >> 5;

#pragma unroll
    for (int k2 = 0; k2 < 16; k2++) {
        int j = tid + k2 * 256;
        svec[j] = __half2float(g_vsh[p][j]) * (1.0f / VS2);    // true v
    }
    __syncthreads();

    const float4* sv4 = (const float4*)svec;
    double dacc = 0.0;
#pragma unroll
    for (int rr = 0; rr < 4; rr++) {
        int row = c * 32 + w * 4 + rr;
        const uint2* Kr = (const uint2*)(g_K8 + (size_t)p * NN * NN + (size_t)row * NN) + lane;
        float acc = 0.0f;
#pragma unroll 2
        for (int i = 0; i < 16; i++) {
            uint2 kr = __ldcs(Kr + i * 32);
            float4 v0 = sv4[(lane + i * 32) * 2];
            float4 v1 = sv4[(lane + i * 32) * 2 + 1];
            float f[8];
            dec4f(kr.x, f);
            dec4f(kr.y, f + 4);
            float vv[8] = {v0.x, v0.y, v0.z, v0.w, v1.x, v1.y, v1.z, v1.w};
#pragma unroll
            for (int j = 0; j < 8; j++) {
                float cc = -REGC * __logf(fmaxf(f[j], 1e-30f));
                acc = fmaf(f[j] * cc, vv[j], acc);
            }
        }
#pragma unroll
        for (int o = 16; o; o >>= 1) acc += __shfl_xor_sync(0xffffffffu, acc, o);
        if (lane == 0) dacc += (double)acc * (double)g_u[p][row];
    }
    if (lane == 0) sred[w] = dacc;
    __syncthreads();
    if (tid == 0) {
        double s = 0.0;
#pragma unroll
        for (int i = 0; i < 8; i++) s += sred[i];
        g_part[p * GRID_SINK + c] = s;
    }
}

// ---------------- final reduction (also resets barrier counter) ----------------
__global__ void final_kernel(float* out) {
    __shared__ double sd[128];
    int t = threadIdx.x;
    if (t == 0) g_cnt = 0u;                 // reset for next graph replay
    double s = g_part[t] + g_part[t + 128] + g_part[t + 256];
    sd[t] = s;
    __syncthreads();
    for (int o = 64; o; o >>= 1) {
        if (t < o) sd[t] += sd[t + o];
        __syncthreads();
    }
    if (t == 0) out[0] = (float)(sd[0] / 3.0);
}

// ---------------- launch -------------------------------------------------------
extern "C" void kernel_launch(void* const* d_in, const int* in_sizes, int n_in,
                              void* d_out, int out_size) {
    const float* z0 = (const float*)d_in[0];
    const float* z1 = (const float*)d_in[1];
    const float* z2 = (const float*)d_in[2];

    rowsq_kernel<<<1536, 256>>>(z0, z1, z2);
    build_kernel<<<dim3(64, 64, 3), 256>>>(z0, z1, z2);
    sinkhorn_kernel<<<GRID_SINK, 512>>>();
    loss_kernel<<<dim3(GRID_SINK, 3), 256>>>();
    final_kernel<<<1, 128>>>((float*)d_out);
}

// round 17
// speedup vs baseline: 1.3006x; 1.3006x over previous
#include <cuda_runtime.h>
#include <cstdint>
#include <cuda_fp16.h>
#include <cuda_bf16.h>
#include <cuda_fp8.h>

#define NN 4096
#define DD 128
#define ITERS 100
#define GRID_SINK 128
#define EPSV 1e-8f
#define MUV (1.0f / 4096.0f)
#define REGC 0.05f
#define USF 64.0f             // u staging scale (half-safe)
#define VS2 1048576.0f        // v storage scale (2^20)

// ---------------- static device scratch (allocation-free rule) ----------------
__device__ __align__(256) unsigned char g_K8[3ULL * NN * NN];  // 48 MB fp8 e4m3
__device__ __align__(256) float g_u[3][NN];                    // true u
__device__ __align__(256) float g_vs[3][NN];                   // v * VS2
__device__ __align__(256) float g_tau[3][GRID_SINK][NN];       // outer-product partials
__device__ __align__(256) float g_sq[3][NN];
__device__ double g_part[3 * GRID_SINK];
__device__ unsigned g_cnt = 0;          // monotonic barrier counter (reset in final_kernel)

// ---------------- fp8 e4m3 helpers ---------------------------------------------
__device__ __forceinline__ unsigned short enc2(float a, float b) {
    return __nv_cvt_float2_to_fp8x2(make_float2(a, b), __NV_SATFINITE, __NV_E4M3);
}

__device__ __forceinline__ __half2 dec2h(unsigned short s) {
    __half2_raw r = __nv_cvt_fp8x2_to_halfraw2((__nv_fp8x2_storage_t)s, __NV_E4M3);
    return *reinterpret_cast<__half2*>(&r);
}

__device__ __forceinline__ void dec16(uint4 k, __half2* h) {
    h[0] = dec2h((unsigned short)(k.x & 0xFFFFu));
    h[1] = dec2h((unsigned short)(k.x >> 16));
    h[2] = dec2h((unsigned short)(k.y & 0xFFFFu));
    h[3] = dec2h((unsigned short)(k.y >> 16));
    h[4] = dec2h((unsigned short)(k.z & 0xFFFFu));
    h[5] = dec2h((unsigned short)(k.z >> 16));
    h[6] = dec2h((unsigned short)(k.w & 0xFFFFu));
    h[7] = dec2h((unsigned short)(k.w >> 16));
}

__device__ __forceinline__ void dec8(uint2 k, __half2* h) {
    h[0] = dec2h((unsigned short)(k.x & 0xFFFFu));
    h[1] = dec2h((unsigned short)(k.x >> 16));
    h[2] = dec2h((unsigned short)(k.y & 0xFFFFu));
    h[3] = dec2h((unsigned short)(k.y >> 16));
}

__device__ __forceinline__ void dec4f(unsigned x, float* f) {
    float2 a = __half22float2(dec2h((unsigned short)(x & 0xFFFFu)));
    float2 b = __half22float2(dec2h((unsigned short)(x >> 16)));
    f[0] = a.x; f[1] = a.y; f[2] = b.x; f[3] = b.y;
}

// ---------------- grid-wide barrier (monotonic counter) ------------------------
__device__ __forceinline__ void grid_barrier_t(unsigned target) {
    __syncthreads();
    if (threadIdx.x == 0) {
        __threadfence();                       // release my stores
        atomicAdd(&g_cnt, 1u);
        while (*(volatile unsigned*)&g_cnt < target) { }
        __threadfence();                       // acquire (CCTL.IVALL: L1 flush)
    }
    __syncthreads();
}

// ---------------- row squared norms --------------------------------------------
__global__ void rowsq_kernel(const float* __restrict__ z0, const float* __restrict__ z1,
                             const float* __restrict__ z2) {
    int gw = (blockIdx.x * blockDim.x + threadIdx.x) >> 5;
    int lane = threadIdx.x & 31;
    int which = gw >> 12, row = gw & 4095;
    const float* src = which == 0 ? z0 : (which == 1 ? z1 : z2);
    float4 v = *(const float4*)(src + (size_t)row * DD + lane * 4);
    float s = v.x * v.x + v.y * v.y + v.z * v.z + v.w * v.w;
#pragma unroll
    for (int o = 16; o; o >>= 1) s += __shfl_xor_sync(0xffffffffu, s, o);
    if (lane == 0) g_sq[which][row] = s;
}

// ---------------- build K (fp8 e4m3) — tensor-core MMA (LDSM + HMMA) -----------
// CTA: 64x64 output tile. 8 warps in 4x2: warp tile 16 rows x 32 cols (4 n8-tiles).
// x tile [64][128] bf16 row-major (pitch 272B), y tile same. fp32 accumulators.
#define XPITCH 272
__global__ void __launch_bounds__(256) build_kernel(const float* __restrict__ z0,
                                                    const float* __restrict__ z1,
                                                    const float* __restrict__ z2) {
    __shared__ __align__(16) unsigned char sbuf[2 * 64 * XPITCH + 4096];
    unsigned char* sx = sbuf;
    unsigned char* sy = sbuf + 64 * XPITCH;
    unsigned char* stg = sbuf + 2 * 64 * XPITCH;   // 64x64 fp8 staging

    const int pa[3] = {0, 0, 1};
    const int pb[3] = {1, 2, 2};
    const float* zz[3] = {z0, z1, z2};
    const int p = blockIdx.z;
    const float* x = zz[pa[p]];
    const float* y = zz[pb[p]];

    const int tid = threadIdx.x;
    const int lane = tid & 31, w = tid >> 5;
    const int row0 = blockIdx.y << 6, col0 = blockIdx.x << 6;

    // ---- load 64x128 fp32 tiles, convert to bf16 ----
#pragma unroll
    for (int q = 0; q < 8; q++) {
        int idx = tid + (q << 8);            // 0..2047 float4 slots
        int r = idx >> 5, k4 = idx & 31;     // 32 float4 per row
        float4 a = *(const float4*)(x + (size_t)(row0 + r) * DD + k4 * 4);
        __nv_bfloat162 a0 = __float22bfloat162_rn(make_float2(a.x, a.y));
        __nv_bfloat162 a1 = __float22bfloat162_rn(make_float2(a.z, a.w));
        uint2 pk;
        pk.x = *reinterpret_cast<unsigned*>(&a0);
        pk.y = *reinterpret_cast<unsigned*>(&a1);
        *(uint2*)(sx + r * XPITCH + k4 * 8) = pk;
        float4 b = *(const float4*)(y + (size_t)(col0 + r) * DD + k4 * 4);
        __nv_bfloat162 b0 = __float22bfloat162_rn(make_float2(b.x, b.y));
        __nv_bfloat162 b1 = __float22bfloat162_rn(make_float2(b.z, b.w));
        uint2 pk2;
        pk2.x = *reinterpret_cast<unsigned*>(&b0);
        pk2.y = *reinterpret_cast<unsigned*>(&b1);
        *(uint2*)(sy + r * XPITCH + k4 * 8) = pk2;
    }
    __syncthreads();

    const int wr = (w >> 1) * 16;          // warp row base (0,16,32,48)
    const int ncb = (w & 1) * 32;          // warp col base (0,32)

    // smem->u32 addresses
    unsigned sx32, sy32;
    {
        unsigned long long t;
        asm("cvta.to.shared.u64 %0, %1;" : "=l"(t) : "l"((void*)sx));
        sx32 = (unsigned)t;
        asm("cvta.to.shared.u64 %0, %1;" : "=l"(t) : "l"((void*)sy));
        sy32 = (unsigned)t;
    }

    float c[4][4] = {};
#pragma unroll
    for (int kk8 = 0; kk8 < 8; kk8++) {
        const int kk = kk8 * 16;
        // A fragment: rows wr..wr+15, k kk..kk+15
        unsigned a0, a1, a2, a3;
        {
            int ts = lane >> 3, gl = lane & 7;
            unsigned addr = sx32 + (unsigned)((wr + (ts & 1) * 8 + gl) * XPITCH +
                                              (kk + (ts >> 1) * 8) * 2);
            asm volatile("ldmatrix.sync.aligned.m8n8.x4.shared.b16 {%0,%1,%2,%3}, [%4];"
                         : "=r"(a0), "=r"(a1), "=r"(a2), "=r"(a3) : "r"(addr));
        }
#pragma unroll
        for (int nt = 0; nt < 4; nt++) {
            unsigned b0, b1;
            {
                int gl = lane & 7, hi = (lane >> 3) & 1;
                unsigned addr = sy32 + (unsigned)((ncb + nt * 8 + gl) * XPITCH +
                                                  (kk + hi * 8) * 2);
                asm volatile("ldmatrix.sync.aligned.m8n8.x2.shared.b16 {%0,%1}, [%2];"
                             : "=r"(b0), "=r"(b1) : "r"(addr));
            }
            asm volatile("mma.sync.aligned.m16n8k16.row.col.f32.bf16.bf16.f32 "
                         "{%0,%1,%2,%3}, {%4,%5,%6,%7}, {%8,%9}, {%0,%1,%2,%3};"
                         : "+f"(c[nt][0]), "+f"(c[nt][1]), "+f"(c[nt][2]), "+f"(c[nt][3])
                         : "r"(a0), "r"(a1), "r"(a2), "r"(a3), "r"(b0), "r"(b1));
        }
    }

    // ---- epilogue: C -> K fp8, staged in smem ----
    {
        int lr = wr + (lane >> 2);           // local row for c0,c1
        float xs0 = g_sq[pa[p]][row0 + lr];
        float xs1 = g_sq[pa[p]][row0 + lr + 8];
#pragma unroll
        for (int nt = 0; nt < 4; nt++) {
            int lc = ncb + nt * 8 + (lane & 3) * 2;    // local col
            float ys0 = g_sq[pb[p]][col0 + lc];
            float ys1 = g_sq[pb[p]][col0 + lc + 1];
            float c00 = fmaxf(xs0 + ys0 - 2.0f * c[nt][0], 0.0f);
            float c01 = fmaxf(xs0 + ys1 - 2.0f * c[nt][1], 0.0f);
            float c10 = fmaxf(xs1 + ys0 - 2.0f * c[nt][2], 0.0f);
            float c11 = fmaxf(xs1 + ys1 - 2.0f * c[nt][3], 0.0f);
            float k00 = fmaxf(__expf(-20.0f * c00), 0.002f);
            float k01 = fmaxf(__expf(-20.0f * c01), 0.002f);
            float k10 = fmaxf(__expf(-20.0f * c10), 0.002f);
            float k11 = fmaxf(__expf(-20.0f * c11), 0.002f);
            *(unsigned short*)(stg + lr * 64 + lc)       = enc2(k00, k01);
            *(unsigned short*)(stg + (lr + 8) * 64 + lc) = enc2(k10, k11);
        }
    }
    __syncthreads();

    // ---- coalesced uint4 store of the 64x64 fp8 tile ----
    {
        int orow = tid >> 2, och = (tid & 3) * 16;
        uint4 val = *(uint4*)(stg + orow * 64 + och);
        *(uint4*)(g_K8 + (size_t)p * NN * NN + (size_t)(row0 + orow) * NN + col0 + och) = val;
    }
}

// ---------------- persistent fused 3-pair Sinkhorn (R9 verbatim) ---------------
__global__ void __launch_bounds__(512, 1) sinkhorn_kernel() {
    __shared__ __half su_h[32];                     // u*USF (half) for my rows
    __shared__ __align__(16) __half svs[NN];        // staged v'' (8 KB)
    __shared__ float sred[12][32];
    const int c = blockIdx.x;
    const int tid = threadIdx.x;
    const int lane = tid & 31, w = tid >> 5;        // 16 warps
    unsigned nb = 0;                                 // barrier index

    auto outerA = [&](int p) {
        const unsigned char* Kb = g_K8 + (size_t)p * NN * NN +
                                  (size_t)(c * 32) * NN + w * 256 + lane * 8;
        __half2 z = __half2half2(__ushort_as_half(0));
        __half2 acc2[4] = {z, z, z, z};
#pragma unroll
        for (int r = 0; r < 32; r += 2) {
            uint2 k0 = *(const uint2*)(Kb + (size_t)r * NN);       // L1 hit after C
            uint2 k1 = *(const uint2*)(Kb + (size_t)(r + 1) * NN);
            __half2 u0 = __half2half2(su_h[r]);
            __half2 u1 = __half2half2(su_h[r + 1]);
            __half2 h0[4], h1[4];
            dec8(k0, h0);
            dec8(k1, h1);
#pragma unroll
            for (int q = 0; q < 4; q++)
                acc2[q] = __hfma2(h0[q], u0, __hfma2(h1[q], u1, acc2[q]));
        }
        float2 f0 = __half22float2(acc2[0]), f1 = __half22float2(acc2[1]);
        float2 f2 = __half22float2(acc2[2]), f3 = __half22float2(acc2[3]);
        float* tp = &g_tau[p][c][w * 256 + lane * 8];
        *(float4*)tp = make_float4(f0.x, f0.y, f1.x, f1.y);
        *(float4*)(tp + 4) = make_float4(f2.x, f2.y, f3.x, f3.y);
    };

    auto phaseB = [&]() {
        if (w < 12) {
            int pb = w >> 2, q = w & 3;
            const float* tp = &g_tau[pb][q * 32][c * 32 + lane];
            float s = 0.0f;
#pragma unroll
            for (int cc = 0; cc < 32; cc++) s += __ldcg(tp + (size_t)cc * NN);
            sred[w][lane] = s;
        }
        __syncthreads();
        if (tid < 96) {
            int pb = tid >> 5, j = tid & 31;
            float tauS = sred[pb * 4][j] + sred[pb * 4 + 1][j] +
                         sred[pb * 4 + 2][j] + sred[pb * 4 + 3][j];
            float tau = tauS * (1.0f / USF);            // true Kt.u
            g_vs[pb][c * 32 + j] = (VS2 * MUV) / (tau + EPSV);
        }
    };

    if (tid < 32) su_h[tid] = __float2half_rn(USF);
    __syncthreads();
#pragma unroll 1
    for (int p = 0; p < 3; p++) outerA(p);
    grid_barrier_t(++nb * GRID_SINK);
    phaseB();
    grid_barrier_t(++nb * GRID_SINK);

    for (int t = 1; t <= ITERS; t++) {
#pragma unroll 1
        for (int p = 0; p < 3; p++) {
            // stage v'' as half
            {
                const float4* gv = (const float4*)g_vs[p];
                float4 x0 = __ldcg(gv + tid * 2);
                float4 x1 = __ldcg(gv + tid * 2 + 1);
                __half2 h0 = __floats2half2_rn(x0.x, x0.y);
                __half2 h1 = __floats2half2_rn(x0.z, x0.w);
                __half2 h2 = __floats2half2_rn(x1.x, x1.y);
                __half2 h3 = __floats2half2_rn(x1.z, x1.w);
                uint4 pk;
                pk.x = *reinterpret_cast<unsigned*>(&h0);
                pk.y = *reinterpret_cast<unsigned*>(&h1);
                pk.z = *reinterpret_cast<unsigned*>(&h2);
                pk.w = *reinterpret_cast<unsigned*>(&h3);
                ((uint4*)svs)[tid] = pk;
            }
            __syncthreads();

            // C-step: 2 rows per warp, K via plain loads (L1-fill)
            {
                int r0 = c * 32 + w * 2;
                const uint4* K0 = (const uint4*)(g_K8 + (size_t)p * NN * NN +
                                                 (size_t)r0 * NN);
                const uint4* K1 = K0 + NN / 16;
                const uint4* sv4 = (const uint4*)svs;
                __half2 z = __half2half2(__ushort_as_half(0));
                __half2 a0 = z, a1 = z, a2 = z, a3 = z;
                __half2 b0 = z, b1 = z, b2 = z, b3 = z;
#pragma unroll
                for (int i = 0; i < 8; i++) {
                    uint4 kr0 = K0[lane + i * 32];
                    uint4 kr1 = K1[lane + i * 32];
                    uint4 v0 = sv4[i * 64 + lane * 2];
                    uint4 v1 = sv4[i * 64 + lane * 2 + 1];
                    __half2 kh0[8], kh1[8];
                    dec16(kr0, kh0);
                    dec16(kr1, kh1);
                    const __half2* vh0 = (const __half2*)&v0;
                    const __half2* vh1 = (const __half2*)&v1;
                    a0 = __hfma2(kh0[0], vh0[0], a0);
                    a1 = __hfma2(kh0[1], vh0[1], a1);
                    a2 = __hfma2(kh0[2], vh0[2], a2);
                    a3 = __hfma2(kh0[3], vh0[3], a3);
                    a0 = __hfma2(kh0[4], vh1[0], a0);
                    a1 = __hfma2(kh0[5], vh1[1], a1);
                    a2 = __hfma2(kh0[6], vh1[2], a2);
                    a3 = __hfma2(kh0[7], vh1[3], a3);
                    b0 = __hfma2(kh1[0], vh0[0], b0);
                    b1 = __hfma2(kh1[1], vh0[1], b1);
                    b2 = __hfma2(kh1[2], vh0[2], b2);
                    b3 = __hfma2(kh1[3], vh0[3], b3);
                    b0 = __hfma2(kh1[4], vh1[0], b0);
                    b1 = __hfma2(kh1[5], vh1[1], b1);
                    b2 = __hfma2(kh1[6], vh1[2], b2);
                    b3 = __hfma2(kh1[7], vh1[3], b3);
                }
                float2 fa0 = __half22float2(a0), fa1 = __half22float2(a1);
                float2 fa2 = __half22float2(a2), fa3 = __half22float2(a3);
                float2 fb0 = __half22float2(b0), fb1 = __half22float2(b1);
                float2 fb2 = __half22float2(b2), fb3 = __half22float2(b3);
                float s0 = (fa0.x + fa0.y) + (fa1.x + fa1.y) +
                           (fa2.x + fa2.y) + (fa3.x + fa3.y);
                float s1 = (fb0.x + fb0.y) + (fb1.x + fb1.y) +
                           (fb2.x + fb2.y) + (fb3.x + fb3.y);
#pragma unroll
                for (int o = 16; o; o >>= 1) {
                    s0 += __shfl_xor_sync(0xffffffffu, s0, o);
                    s1 += __shfl_xor_sync(0xffffffffu, s1, o);
                }
                if (lane == 0) {
                    float u0 = MUV / (s0 * (1.0f / VS2) + EPSV);
                    float u1 = MUV / (s1 * (1.0f / VS2) + EPSV);
                    g_u[p][r0] = u0;
                    g_u[p][r0 + 1] = u1;
                    su_h[w * 2] = __float2half_rn(u0 * USF);
                    su_h[w * 2 + 1] = __float2half_rn(u1 * USF);
                }
            }
            __syncthreads();

            if (t < ITERS) outerA(p);   // L1-hot re-read of the same K block
        }
        if (t < ITERS) {
            grid_barrier_t(++nb * GRID_SINK);
            phaseB();
            grid_barrier_t(++nb * GRID_SINK);
        }
    }
}

// ---------------- loss = sum_ij u_i K_ij C_ij v_j,  C = -reg*ln(K) -------------
__global__ void __launch_bounds__(256) loss_kernel() {
    __shared__ float svec[NN];
    __shared__ double sred[8];
    const int c = blockIdx.x;
    const int p = blockIdx.y;
    const int tid = threadIdx.x;
    const int lane = tid & 31, w = tid >> 5;

#pragma unroll
    for (int k2 = 0; k2 < 16; k2++) {
        int j = tid + k2 * 256;
        svec[j] = g_vs[p][j] * (1.0f / VS2);    // true v
    }
    __syncthreads();

    const float4* sv4 = (const float4*)svec;
    double dacc = 0.0;
#pragma unroll
    for (int rr = 0; rr < 4; rr++) {
        int row = c * 32 + w * 4 + rr;
        const uint2* Kr = (const uint2*)(g_K8 + (size_t)p * NN * NN + (size_t)row * NN) + lane;
        float acc = 0.0f;
#pragma unroll 2
        for (int i = 0; i < 16; i++) {
            uint2 kr = __ldcs(Kr + i * 32);
            float4 v0 = sv4[(lane + i * 32) * 2];
            float4 v1 = sv4[(lane + i * 32) * 2 + 1];
            float f[8];
            dec4f(kr.x, f);
            dec4f(kr.y, f + 4);
            float vv[8] = {v0.x, v0.y, v0.z, v0.w, v1.x, v1.y, v1.z, v1.w};
#pragma unroll
            for (int j = 0; j < 8; j++) {
                float cc = -REGC * __logf(fmaxf(f[j], 1e-30f));
                acc = fmaf(f[j] * cc, vv[j], acc);
            }
        }
#pragma unroll
        for (int o = 16; o; o >>= 1) acc += __shfl_xor_sync(0xffffffffu, acc, o);
        if (lane == 0) dacc += (double)acc * (double)g_u[p][row];
    }
    if (lane == 0) sred[w] = dacc;
    __syncthreads();
    if (tid == 0) {
        double s = 0.0;
#pragma unroll
        for (int i = 0; i < 8; i++) s += sred[i];
        g_part[p * GRID_SINK + c] = s;
    }
}

// ---------------- final reduction (also resets barrier counter) ----------------
__global__ void final_kernel(float* out) {
    __shared__ double sd[128];
    int t = threadIdx.x;
    if (t == 0) g_cnt = 0u;                 // reset for next graph replay
    double s = g_part[t] + g_part[t + 128] + g_part[t + 256];
    sd[t] = s;
    __syncthreads();
    for (int o = 64; o; o >>= 1) {
        if (t < o) sd[t] += sd[t + o];
        __syncthreads();
    }
    if (t == 0) out[0] = (float)(sd[0] / 3.0);
}

// ---------------- launch -------------------------------------------------------
extern "C" void kernel_launch(void* const* d_in, const int* in_sizes, int n_in,
                              void* d_out, int out_size) {
    const float* z0 = (const float*)d_in[0];
    const float* z1 = (const float*)d_in[1];
    const float* z2 = (const float*)d_in[2];

    rowsq_kernel<<<1536, 256>>>(z0, z1, z2);
    build_kernel<<<dim3(64, 64, 3), 256>>>(z0, z1, z2);
    sinkhorn_kernel<<<GRID_SINK, 512>>>();
    loss_kernel<<<dim3(GRID_SINK, 3), 256>>>();
    final_kernel<<<1, 128>>>((float*)d_out);
}